// round 13
// baseline (speedup 1.0000x reference)
#include <cuda_runtime.h>

#define NBLOCKS 296
#define NTHREADS 256

__device__ double g_partials[NBLOCKS];
__device__ unsigned int g_ticket = 0;

__device__ __forceinline__ double warpReduceD(double v) {
    #pragma unroll
    for (int o = 16; o > 0; o >>= 1)
        v += __shfl_down_sync(0xffffffffu, v, o);
    return v;
}

// se3_log from rotation's (trace, vee) + translation -> xi[6]
__device__ __forceinline__ void se3_log_tv(float tr, float vx, float vy, float vz,
                                           float w0, float w1, float w2,
                                           float* xi) {
    float c = 0.5f * (tr - 1.0f);
    c = fminf(fmaxf(c, -1.0f + 1e-7f), 1.0f - 1e-7f);
    float th = acosf(c);
    // sin(acos(c)) = sqrt(1-c^2), exact for th in [0, pi]
    float s = sqrtf(fmaxf(1.0f - c * c, 1e-20f));
    float t2 = th * th;
    float rr = __fdividef(1.0f, 2.0f * s * t2);  // shared reciprocal
    float factor = th * t2 * rr;                 // th/(2s)
    float D = rr * (2.0f * s - (1.0f + c) * th); // 1/t2 - (1+c)/(2 th s)
    float px = factor * vx;
    float py = factor * vy;
    float pz = factor * vz;
    float pd = px * w0 + py * w1 + pz * w2;
    float cx = py * w2 - pz * w1;
    float cy = pz * w0 - px * w2;
    float cz = px * w1 - py * w0;
    xi[0] = w0 - 0.5f * cx + D * (px * pd - t2 * w0);
    xi[1] = w1 - 0.5f * cy + D * (py * pd - t2 * w1);
    xi[2] = w2 - 0.5f * cz + D * (pz * pd - t2 * w2);
    xi[3] = px;
    xi[4] = py;
    xi[5] = pz;
}

// Full per-row loss term via quaternions: returns quad(g)-quad(s) = (g-s)^T P (g+s)
__device__ __forceinline__ float row_q(float2 a0, float2 a1, float2 a2,
                                       float4 q0, float4 q1, float4 q2,
                                       const float* __restrict__ sP) {
    float r0i = a0.x, r1i = a0.y, r2i = a1.x;   // rho_in
    float x = a1.y, y = a2.x, z = a2.y;         // phi_in

    // ---- se3_exp(input) as quaternion (w1q, v1) + left-Jacobian coeffs ----
    float t2 = x * x + y * y + z * z;
    bool small = t2 < 1e-8f;
    float t2s = small ? 1.0f : t2;
    float th = sqrtf(t2s);
    float sh, chh;
    __sincosf(0.5f * th, &sh, &chh);
    float sinth = 2.0f * sh * chh;              // sin(th)
    float rden = __fdividef(1.0f, t2s * th);    // 1/th^3
    // B = (1-cos th)/th^2 = 2 sh^2/th^2 ; C = (th - sin th)/th^3 ; k = sin(th/2)/th
    float Bc = small ? 0.5f - t2 * (1.0f / 24.0f) : 2.0f * sh * sh * th * rden;
    float Cc = small ? (1.0f / 6.0f) - t2 * (1.0f / 120.0f) : (th - sinth) * rden;
    float kq = small ? 0.5f - t2 * (1.0f / 48.0f) : sh * t2s * rden;  // sh/th
    float w1q = small ? 1.0f - t2 * 0.125f : chh;
    float v1x = kq * x, v1y = kq * y, v1z = kq * z;

    // t1 = Jl(phi) @ rho
    float pd = x * r0i + y * r1i + z * r2i;
    float cx = y * r2i - z * r1i;
    float cy = z * r0i - x * r2i;
    float cz = x * r1i - y * r0i;
    float t1x = r0i + Bc * cx + Cc * (x * pd - t2 * r0i);
    float t1y = r1i + Bc * cy + Cc * (y * pd - t2 * r1i);
    float t1z = r2i + Bc * cz + Cc * (z * pd - t2 * r2i);

    // ---- target: trace/vee straight from loads; quaternion qt ----
    float tt0 = q0.w, tt1 = q1.w, tt2 = q2.w;
    float trt = q0.x + q1.y + q2.z;
    float vtx0 = q2.y - q1.z;     // vee(Rt)
    float vty0 = q0.z - q2.x;
    float vtz0 = q1.x - q0.y;
    float s1p = fmaxf(1.0f + trt, 1e-12f);      // = 4 cos^2(th*/2)
    float rs = rsqrtf(s1p);
    float wt = 0.5f * s1p * rs;                 // cos(th*/2)
    float kt = 0.5f * rs;                       // 1/(4 wt)
    float vtx = kt * vtx0, vty = kt * vty0, vtz = kt * vtz0;  // sin(th*/2)*axis

    // ---- compose qm = q1 (x) qt ----
    float wm = w1q * wt - (v1x * vtx + v1y * vty + v1z * vtz);
    float vmx = w1q * vtx + wt * v1x + (v1y * vtz - v1z * vty);
    float vmy = w1q * vty + wt * v1y + (v1z * vtx - v1x * vtz);
    float vmz = w1q * vtz + wt * v1z + (v1x * vty - v1y * vtx);
    float trM = fmaf(4.0f * wm, wm, -1.0f);     // 4 wm^2 - 1
    float w4 = 4.0f * wm;
    float mvx = w4 * vmx, mvy = w4 * vmy, mvz = w4 * vmz;  // vee(M)

    // ---- tm = R1 @ tt + t1 via quaternion rotation ----
    float ux = v1y * tt2 - v1z * tt1;
    float uy = v1z * tt0 - v1x * tt2;
    float uz = v1x * tt1 - v1y * tt0;
    float tmx = tt0 + 2.0f * (w1q * ux + (v1y * uz - v1z * uy)) + t1x;
    float tmy = tt1 + 2.0f * (w1q * uy + (v1z * ux - v1x * uz)) + t1y;
    float tmz = tt2 + 2.0f * (w1q * uz + (v1x * uy - v1y * ux)) + t1z;

    // ---- logs ----
    float xg[6], xs[6];
    se3_log_tv(trM, mvx, mvy, mvz, tmx, tmy, tmz, xg);
    se3_log_tv(trt, vtx0, vty0, vtz0, tt0, tt1, tt2, xs);

    float u[6], v[6];
    #pragma unroll
    for (int i = 0; i < 6; i++) { u[i] = xg[i] - xs[i]; v[i] = xg[i] + xs[i]; }
    float q = 0.0f;
    #pragma unroll
    for (int i = 0; i < 6; i++) {
        float w = 0.0f;
        #pragma unroll
        for (int j = 0; j < 6; j++)
            w = fmaf(sP[i * 6 + j], v[j], w);
        q = fmaf(u[i], w, q);
    }
    return q;
}

__global__ void __launch_bounds__(NTHREADS, 2)
se3_loss_main(const float* __restrict__ inp, const float* __restrict__ T,
              const float* __restrict__ P, float* __restrict__ out, int B) {
    __shared__ float sP[36];
    if (threadIdx.x < 36) sP[threadIdx.x] = P[threadIdx.x];
    __syncthreads();

    const int S = NBLOCKS * NTHREADS;
    int b = blockIdx.x * NTHREADS + threadIdx.x;
    double acc = 0.0;

    // ---- preload inp for the first pair (chain-entry data) ----
    float2 a0, a1, a2, c0, c1, c2;
    {
        bool v0 = b < B, v1 = b + S < B;
        const float2* ipa = (const float2*)(inp + 6 * (v0 ? b : 0));
        const float2* ipb = (const float2*)(inp + 6 * (v1 ? (b + S) : 0));
        a0 = ipa[0]; a1 = ipa[1]; a2 = ipa[2];
        c0 = ipb[0]; c1 = ipb[1]; c2 = ipb[2];
    }

    int bb = b;
    for (; bb + S < B; bb += 2 * S) {
        int b1 = bb + S;
        const float4* Tpa = (const float4*)(T + 16 * bb);
        const float4* Tpb = (const float4*)(T + 16 * b1);
        float4 p0 = Tpa[0], p1 = Tpa[1], p2 = Tpa[2];
        float4 r0 = Tpb[0], r1 = Tpb[1], r2 = Tpb[2];

        // prefetch next pair's inp (chain-entry data for next iteration)
        int nb = bb + 2 * S;
        bool nv0 = nb < B, nv1 = nb + S < B;
        const float2* nipa = (const float2*)(inp + 6 * (nv0 ? nb : 0));
        const float2* nipb = (const float2*)(inp + 6 * (nv1 ? (nb + S) : 0));
        float2 e0 = nipa[0], e1 = nipa[1], e2 = nipa[2];
        float2 f0 = nipb[0], f1 = nipb[1], f2 = nipb[2];

        float qa = row_q(a0, a1, a2, p0, p1, p2, sP);
        float qb = row_q(c0, c1, c2, r0, r1, r2, sP);
        acc += (double)qa + (double)qb;

        a0 = e0; a1 = e1; a2 = e2;
        c0 = f0; c1 = f1; c2 = f2;
    }
    // ---- tail: at most one row left (its inp is already in a0..a2) ----
    if (bb < B) {
        const float4* Tpa = (const float4*)(T + 16 * bb);
        float4 p0 = Tpa[0], p1 = Tpa[1], p2 = Tpa[2];
        acc += (double)row_q(a0, a1, a2, p0, p1, p2, sP);
    }

    // ---- block reduction ----
    acc = warpReduceD(acc);
    __shared__ double sw[NTHREADS / 32];
    if ((threadIdx.x & 31) == 0) sw[threadIdx.x >> 5] = acc;
    __syncthreads();
    __shared__ bool amLast;
    if (threadIdx.x < 32) {
        double v = (threadIdx.x < NTHREADS / 32) ? sw[threadIdx.x] : 0.0;
        v = warpReduceD(v);
        if (threadIdx.x == 0) {
            g_partials[blockIdx.x] = v;
            __threadfence();
            unsigned int t = atomicInc(&g_ticket, NBLOCKS - 1);  // self-resetting
            amLast = (t == NBLOCKS - 1);
        }
    }
    __syncthreads();

    // ---- last block reduces all partials (fixed order -> deterministic) ----
    if (amLast) {
        double v = 0.0;
        for (int i = threadIdx.x; i < NBLOCKS; i += NTHREADS)
            v += g_partials[i];
        v = warpReduceD(v);
        if ((threadIdx.x & 31) == 0) sw[threadIdx.x >> 5] = v;
        __syncthreads();
        if (threadIdx.x < 32) {
            double t = (threadIdx.x < NTHREADS / 32) ? sw[threadIdx.x] : 0.0;
            t = warpReduceD(t);
            if (threadIdx.x == 0)
                out[0] = (float)(0.5 / (double)B * t);
        }
    }
}

extern "C" void kernel_launch(void* const* d_in, const int* in_sizes, int n_in,
                              void* d_out, int out_size) {
    const float* inp = (const float*)d_in[0];        // (B, 6)
    const float* T   = (const float*)d_in[1];        // (B, 4, 4)
    const float* P   = (const float*)d_in[2];        // (6, 6)
    float* out = (float*)d_out;
    int B = in_sizes[0] / 6;
    se3_loss_main<<<NBLOCKS, NTHREADS>>>(inp, T, P, out, B);
}